// round 11
// baseline (speedup 1.0000x reference)
#include <cuda_runtime.h>
#include <cuda_bf16.h>
#include <cstdint>

#define HGT 512
#define WID 512
#define NB 2
#define NCH 64
#define NPTS 131072
#define NMASK 131072

__device__ __align__(16) float g_mask[NB * HGT * WID];
__device__ int g_mode[2];

// ---------------------------------------------------------------------------
// Helpers
// ---------------------------------------------------------------------------
__device__ __forceinline__ uint32_t smem_u32(const void* p) {
    uint32_t a;
    asm("{ .reg .u64 t; cvta.to.shared.u64 t, %1; cvt.u32.u64 %0, t; }"
        : "=r"(a) : "l"(p));
    return a;
}
__device__ __forceinline__ uint32_t pack_bf(__nv_bfloat16 a, __nv_bfloat16 b) {
    __nv_bfloat162 t(a, b);
    return *reinterpret_cast<uint32_t*>(&t);
}
__device__ __forceinline__ void ldsm_x4(uint32_t* r, uint32_t addr) {
    asm volatile("ldmatrix.sync.aligned.m8n8.x4.shared.b16 {%0,%1,%2,%3}, [%4];"
                 : "=r"(r[0]), "=r"(r[1]), "=r"(r[2]), "=r"(r[3]) : "r"(addr));
}
__device__ __forceinline__ void ldsm_x4_t(uint32_t* r, uint32_t addr) {
    asm volatile("ldmatrix.sync.aligned.m8n8.x4.trans.shared.b16 {%0,%1,%2,%3}, [%4];"
                 : "=r"(r[0]), "=r"(r[1]), "=r"(r[2]), "=r"(r[3]) : "r"(addr));
}
__device__ __forceinline__ void mma_bf16(float* c, const uint32_t* a,
                                         uint32_t b0, uint32_t b1) {
    asm volatile(
        "mma.sync.aligned.m16n8k16.row.col.f32.bf16.bf16.f32 "
        "{%0,%1,%2,%3}, {%4,%5,%6,%7}, {%8,%9}, {%0,%1,%2,%3};"
        : "+f"(c[0]), "+f"(c[1]), "+f"(c[2]), "+f"(c[3])
        : "r"(a[0]), "r"(a[1]), "r"(a[2]), "r"(a[3]), "r"(b0), "r"(b1));
}

// ---------------------------------------------------------------------------
// Index-format detection + robust row loader
// ---------------------------------------------------------------------------
__device__ __forceinline__ int detect_mode(const void* p) {
    const unsigned* w = (const unsigned*)p;
    bool hi_zero = true;
#pragma unroll
    for (int k = 0; k < 16; ++k) hi_zero &= (w[2 * k + 1] == 0u);
    if (hi_zero) return 0;
    bool small = true;
#pragma unroll
    for (int k = 0; k < 16; ++k) small &= (w[k] < 0x10000u);
    return small ? 1 : 2;
}

__global__ void detect_kernel(const void* idx, const void* midx) {
    if (threadIdx.x == 0) g_mode[0] = detect_mode(idx);
    if (threadIdx.x == 1) g_mode[1] = detect_mode(midx);
}

__device__ __forceinline__ void load_row3(const void* p, int i, int mode,
                                          int& b, int& y, int& x) {
    if (mode == 0) {
        const long long* q = (const long long*)p + 3 * (size_t)i;
        b = (int)q[0]; y = (int)q[1]; x = (int)q[2];
    } else if (mode == 1) {
        const int* q = (const int*)p + 3 * (size_t)i;
        b = q[0]; y = q[1]; x = q[2];
    } else {
        const float* q = (const float*)p + 3 * (size_t)i;
        b = (int)q[0]; y = (int)q[1]; x = (int)q[2];
    }
    b = b < 0 ? 0 : (b > NB - 1 ? NB - 1 : b);
    y = y < 0 ? 0 : (y > HGT - 1 ? HGT - 1 : y);
    x = x < 0 ? 0 : (x > WID - 1 ? WID - 1 : x);
}

// ---------------------------------------------------------------------------
// Kernel 1 + 2: zero accumulators, scatter mask.
// ---------------------------------------------------------------------------
__global__ void zero_kernel(float4* __restrict__ out4, int n_out4) {
    int i = blockIdx.x * blockDim.x + threadIdx.x;
    float4 z = make_float4(0.f, 0.f, 0.f, 0.f);
    if (i < n_out4) out4[i] = z;
    const int n_mask4 = NB * HGT * WID / 4;
    if (i < n_mask4) reinterpret_cast<float4*>(g_mask)[i] = z;
}

__global__ void mask_scatter_kernel(const void* __restrict__ mi,
                                    const float* __restrict__ mv) {
    int i = blockIdx.x * blockDim.x + threadIdx.x;
    if (i < NMASK) {
        int b, y, x;
        load_row3(mi, i, g_mode[1], b, y, x);
        atomicAdd(&g_mask[(b * HGT + y) * WID + x], mv[i]);
    }
}

// ---------------------------------------------------------------------------
// Kernel 3: warp-level mma.sync bf16 3-pass split GEMM + red.v2 scatter.
// Block = 128 points (8 warps x 16-row stripes), N=64, K=64, 9 taps.
// SMEM layout (dynamic, byte offsets):
//   coords  : 3 x 128 int                         @ 0     (1536 B)
//   A hi/lo : 128 rows x 72 halfs (144 B pitch)   @ 1536 / 19968
//   B hi/lo :  64 rows x 72 halfs (144 B pitch)   @ 38400 / 47616
// 144-B pitch staggers the 16-B ldmatrix chunks across bank groups
// (4 banks per row step) -> conflict-free ldmatrix.
// ---------------------------------------------------------------------------
#define SM_AHI 1536
#define SM_ALO 19968
#define SM_BHI 38400
#define SM_BLO 47616
#define SM_TOTAL 56832
#define PITCH 144

__global__ __launch_bounds__(256, 3)
void conv_mma_kernel(const float* __restrict__ values,
                     const float* __restrict__ kern,
                     const void* __restrict__ idx,
                     float* __restrict__ dense) {
    extern __shared__ char smem[];
    const uint32_t sb = smem_u32(smem);
    const int tid = threadIdx.x;
    const int wid = tid >> 5;
    const int lane = tid & 31;
    const int m0 = blockIdx.x * 128;

    int* Pb = reinterpret_cast<int*>(smem);
    int* Py = Pb + 128;
    int* Px = Py + 128;

    // Stage coords.
    for (int i = tid; i < 128; i += 256) {
        int b, y, x;
        load_row3(idx, m0 + i, g_mode[0], b, y, x);
        Pb[i] = b; Py[i] = y; Px[i] = x;
    }
    // Stage A hi/lo bf16 (once per block). i enumerates m*16 + kc/4.
    {
        const float4* v4 = reinterpret_cast<const float4*>(values) + (size_t)m0 * 16;
        for (int i = tid; i < 2048; i += 256) {
            int m = i >> 4, kc = (i & 15) << 2;
            float4 v = v4[i];
            __nv_bfloat16 h0 = __float2bfloat16(v.x), h1 = __float2bfloat16(v.y);
            __nv_bfloat16 h2 = __float2bfloat16(v.z), h3 = __float2bfloat16(v.w);
            __nv_bfloat16 l0 = __float2bfloat16(v.x - __bfloat162float(h0));
            __nv_bfloat16 l1 = __float2bfloat16(v.y - __bfloat162float(h1));
            __nv_bfloat16 l2 = __float2bfloat16(v.z - __bfloat162float(h2));
            __nv_bfloat16 l3 = __float2bfloat16(v.w - __bfloat162float(h3));
            uint32_t off = (uint32_t)(m * PITCH + kc * 2);
            *reinterpret_cast<uint32_t*>(smem + SM_AHI + off) = pack_bf(h0, h1);
            *reinterpret_cast<uint32_t*>(smem + SM_AHI + off + 4) = pack_bf(h2, h3);
            *reinterpret_cast<uint32_t*>(smem + SM_ALO + off) = pack_bf(l0, l1);
            *reinterpret_cast<uint32_t*>(smem + SM_ALO + off + 4) = pack_bf(l2, l3);
        }
    }

    // ldmatrix per-lane base addresses.
    const uint32_t a_base = sb + (uint32_t)((wid * 16 + (lane & 15)) * PITCH +
                                            ((lane >> 4) << 4));
    const uint32_t b_base = sb + (uint32_t)((lane & 15) * PITCH +
                                            ((lane >> 4) << 4));
    // Scatter ownership: rows mA = wid*16+g and mA+8, cols tig*2 (+nt*8).
    const int g = lane >> 2, tig = lane & 3;
    const int mA = wid * 16 + g;
    __syncthreads();
    const int pbA = Pb[mA], pyA = Py[mA], pxA = Px[mA];
    const int pbB = Pb[mA + 8], pyB = Py[mA + 8], pxB = Px[mA + 8];

#pragma unroll 1
    for (int tap = 0; tap < 9; ++tap) {
        __syncthreads();   // prior tap's ldmatrix reads done before B overwrite
        {   // Stage B hi/lo: kern[tap] is [k][n] row-major. i = k*16 + nc/4.
            const float4* kt4 =
                reinterpret_cast<const float4*>(kern + (size_t)tap * NCH * NCH);
            for (int i = tid; i < 1024; i += 256) {
                int k = i >> 4, nc = (i & 15) << 2;
                float4 v = kt4[i];
                __nv_bfloat16 h0 = __float2bfloat16(v.x), h1 = __float2bfloat16(v.y);
                __nv_bfloat16 h2 = __float2bfloat16(v.z), h3 = __float2bfloat16(v.w);
                __nv_bfloat16 l0 = __float2bfloat16(v.x - __bfloat162float(h0));
                __nv_bfloat16 l1 = __float2bfloat16(v.y - __bfloat162float(h1));
                __nv_bfloat16 l2 = __float2bfloat16(v.z - __bfloat162float(h2));
                __nv_bfloat16 l3 = __float2bfloat16(v.w - __bfloat162float(h3));
                uint32_t off = (uint32_t)(k * PITCH + nc * 2);
                *reinterpret_cast<uint32_t*>(smem + SM_BHI + off) = pack_bf(h0, h1);
                *reinterpret_cast<uint32_t*>(smem + SM_BHI + off + 4) = pack_bf(h2, h3);
                *reinterpret_cast<uint32_t*>(smem + SM_BLO + off) = pack_bf(l0, l1);
                *reinterpret_cast<uint32_t*>(smem + SM_BLO + off + 4) = pack_bf(l2, l3);
            }
        }
        __syncthreads();

        float acc[8][4];
#pragma unroll
        for (int nt = 0; nt < 8; ++nt)
#pragma unroll
            for (int j = 0; j < 4; ++j) acc[nt][j] = 0.f;

        // 3 passes: Ahi*Bhi + Ahi*Blo + Alo*Bhi.
#pragma unroll
        for (int pass = 0; pass < 3; ++pass) {
            const uint32_t abase = (pass < 2) ? (uint32_t)SM_AHI : (uint32_t)SM_ALO;
            const uint32_t bbase = (pass == 1) ? (uint32_t)SM_BLO : (uint32_t)SM_BHI;
#pragma unroll
            for (int ks = 0; ks < 4; ++ks) {
                uint32_t a[4];
                ldsm_x4(a, a_base + abase + ks * 32);
#pragma unroll
                for (int ntp = 0; ntp < 4; ++ntp) {
                    uint32_t b[4];
                    ldsm_x4_t(b, b_base + bbase + ks * (16 * PITCH) + ntp * 32);
                    mma_bf16(acc[2 * ntp], a, b[0], b[1]);
                    mma_bf16(acc[2 * ntp + 1], a, b[2], b[3]);
                }
            }
        }

        // Scatter D frags: thread owns (rows mA, mA+8) x cols (nt*8 + tig*2).
        const int dy = tap / 3 - 1;
        const int dx = tap % 3 - 1;
        {
            int sy = pyA + dy; sy = sy < 0 ? 0 : (sy > HGT - 1 ? HGT - 1 : sy);
            int sx = pxA + dx; sx = sx < 0 ? 0 : (sx > WID - 1 ? WID - 1 : sx);
            float* p = dense + (((size_t)pbA * HGT + sy) * WID + sx) * NCH + tig * 2;
#pragma unroll
            for (int nt = 0; nt < 8; ++nt)
                asm volatile("red.global.add.v2.f32 [%0], {%1, %2};"
                             :: "l"(p + nt * 8), "f"(acc[nt][0]), "f"(acc[nt][1])
                             : "memory");
        }
        {
            int sy = pyB + dy; sy = sy < 0 ? 0 : (sy > HGT - 1 ? HGT - 1 : sy);
            int sx = pxB + dx; sx = sx < 0 ? 0 : (sx > WID - 1 ? WID - 1 : sx);
            float* p = dense + (((size_t)pbB * HGT + sy) * WID + sx) * NCH + tig * 2;
#pragma unroll
            for (int nt = 0; nt < 8; ++nt)
                asm volatile("red.global.add.v2.f32 [%0], {%1, %2};"
                             :: "l"(p + nt * 8), "f"(acc[nt][2]), "f"(acc[nt][3])
                             : "memory");
        }
    }
}

// ---------------------------------------------------------------------------
// Kernel 4: epilogue  out = (dense + mask*bias) * mask
// ---------------------------------------------------------------------------
__global__ void epilogue_kernel(float4* __restrict__ out4,
                                const float4* __restrict__ bias4) {
    int i = blockIdx.x * blockDim.x + threadIdx.x;
    float m = g_mask[i >> 4];
    float4 d = out4[i];
    float4 bv = __ldg(&bias4[i & 15]);
    d.x = (d.x + m * bv.x) * m;
    d.y = (d.y + m * bv.y) * m;
    d.z = (d.z + m * bv.z) * m;
    d.w = (d.w + m * bv.w) * m;
    out4[i] = d;
}

// ---------------------------------------------------------------------------
extern "C" void kernel_launch(void* const* d_in, const int* in_sizes, int n_in,
                              void* d_out, int out_size) {
    const float* values = nullptr;
    const float* kern = nullptr;
    const float* bias = nullptr;
    const float* mask_values = nullptr;
    const void* indices = nullptr;
    const void* mask_indices = nullptr;

    for (int i = 0; i < n_in; ++i) {
        int s = in_sizes[i];
        if (s == 8388608)      values = (const float*)d_in[i];
        else if (s == 36864)   kern = (const float*)d_in[i];
        else if (s == 64)      bias = (const float*)d_in[i];
        else if (s == 131072)  mask_values = (const float*)d_in[i];
        else if (s == 393216 || s == 786432) {
            if (!indices) indices = d_in[i];
            else          mask_indices = d_in[i];
        }
    }
    if (!values)       values       = (const float*)d_in[0];
    if (!kern)         kern         = (const float*)d_in[1];
    if (!bias)         bias         = (const float*)d_in[2];
    if (!mask_values)  mask_values  = (const float*)d_in[3];
    if (!indices)      indices      = d_in[4];
    if (!mask_indices) mask_indices = d_in[5];

    float* out = (float*)d_out;
    const int n_out4 = NB * HGT * WID * NCH / 4;  // 8388608

    static bool attr_set = false;
    if (!attr_set) {
        cudaFuncSetAttribute(conv_mma_kernel,
                             cudaFuncAttributeMaxDynamicSharedMemorySize, SM_TOTAL);
        attr_set = true;
    }

    detect_kernel<<<1, 32>>>(indices, mask_indices);
    zero_kernel<<<(n_out4 + 255) / 256, 256>>>((float4*)out, n_out4);
    mask_scatter_kernel<<<(NMASK + 255) / 256, 256>>>(mask_indices, mask_values);
    conv_mma_kernel<<<NPTS / 128, 256, SM_TOTAL>>>(values, kern, indices, out);
    epilogue_kernel<<<n_out4 / 256, 256>>>((float4*)out, (const float4*)bias);
}